// round 2
// baseline (speedup 1.0000x reference)
#include <cuda_runtime.h>

// ---------------------------------------------------------------------------
// SwinStyleAttention: B=8, C=128, H=W=256, WS=8, SS=4, HEADS=4, DH=32
// One CTA per window (8192 windows), 256 threads (8 warps).
// TF32 mma.sync path with explicit cvt.rna rounding everywhere.
// ---------------------------------------------------------------------------

#define SCALE_F 0.17677669529663687f   // 32^-0.5

#define XP 130                          // row stride (floats) for token-major tiles

// smem layout (floats)
#define OFF_A   0                       // X -> V -> Y         (64 x XP)
#define OFF_C   8320                    // Q -> O              (64 x XP)
#define OFF_E   16640                   // K                   (64 x XP)
#define OFF_W0  24960                   // Wq / Wv / P         (128 x 128, swizzled)
#define OFF_W1  41344                   // Wk / Wproj          (128 x 128, swizzled)
#define SMEM_FLOATS 57728
#define SMEM_BYTES (SMEM_FLOATS * 4)    // 230,912 B

__device__ float g_wqkv[128 * 384];
__device__ float g_wproj[128 * 128];

__device__ __forceinline__ unsigned f2tf(float f) {
    unsigned u;
    asm("cvt.rna.tf32.f32 %0, %1;" : "=r"(u) : "f"(f));
    return u;
}

__device__ __forceinline__ void mma8(float c[4], unsigned a0, unsigned a1,
                                     unsigned a2, unsigned a3,
                                     unsigned b0, unsigned b1) {
    asm volatile(
        "mma.sync.aligned.m16n8k8.row.col.f32.tf32.tf32.f32 "
        "{%0,%1,%2,%3},{%4,%5,%6,%7},{%8,%9},{%0,%1,%2,%3};"
        : "+f"(c[0]), "+f"(c[1]), "+f"(c[2]), "+f"(c[3])
        : "r"(a0), "r"(a1), "r"(a2), "r"(a3), "r"(b0), "r"(b1));
}

__device__ __forceinline__ void cp_async16(float* dst, const float* src) {
    unsigned d = static_cast<unsigned>(__cvta_generic_to_shared(dst));
    asm volatile("cp.async.cg.shared.global [%0], [%1], 16;" :: "r"(d), "l"(src));
}

// Stage a 128x128 fp32 weight chunk into smem with an XOR-8 swizzle on 8-col
// granularity (conflict-free B-fragment reads).
__device__ __forceinline__ void stage_w(float* sW, const float* src, int rowStride, int tid) {
#pragma unroll
    for (int i = 0; i < 16; i++) {
        int idx  = i * 256 + tid;
        int row  = idx >> 5;            // 0..127
        int col  = (idx & 31) << 2;     // 0..124 step 4
        int scol = col ^ ((row & 3) << 3);
        cp_async16(sW + row * 128 + scol, src + row * rowStride + col);
    }
    asm volatile("cp.async.commit_group;" ::: "memory");
}

__device__ __forceinline__ void wait_cp() {
    asm volatile("cp.async.wait_group 0;" ::: "memory");
}

// D[64,128] = A[64,128] @ W[128,128]; warp grid 4(M) x 2(N), warp tile 16x64.
template <bool ROUND, bool BIAS, bool SYNCSTORE>
__device__ __forceinline__ void gemm64(const float* __restrict__ sA,
                                       const float* __restrict__ sW,
                                       float* __restrict__ sDst,
                                       int wid, int lane, float scale,
                                       const float* __restrict__ bias) {
    const int wm = wid >> 1, wn = wid & 1;
    const int rbase = wm * 16, nbase = wn * 64;
    const int g = lane >> 2, tg = lane & 3;

    float acc[8][4];
#pragma unroll
    for (int nt = 0; nt < 8; nt++) {
        acc[nt][0] = 0.f; acc[nt][1] = 0.f; acc[nt][2] = 0.f; acc[nt][3] = 0.f;
    }

    const float* Ar0 = sA + (rbase + g) * XP;
    const float* Ar1 = sA + (rbase + g + 8) * XP;

#pragma unroll
    for (int k0 = 0; k0 < 128; k0 += 8) {
        unsigned a0 = __float_as_uint(Ar0[k0 + tg]);
        unsigned a1 = __float_as_uint(Ar1[k0 + tg]);
        unsigned a2 = __float_as_uint(Ar0[k0 + tg + 4]);
        unsigned a3 = __float_as_uint(Ar1[k0 + tg + 4]);
        const float* B0 = sW + (k0 + tg) * 128;
        const float* B1 = sW + (k0 + tg + 4) * 128;
#pragma unroll
        for (int nt = 0; nt < 8; nt++) {
            int n = (nbase + nt * 8 + g) ^ (tg << 3);
            mma8(acc[nt], a0, a1, a2, a3,
                 __float_as_uint(B0[n]), __float_as_uint(B1[n]));
        }
    }

    if (SYNCSTORE) __syncthreads();

#pragma unroll
    for (int nt = 0; nt < 8; nt++) {
        int r0 = rbase + g;
        int c0 = nbase + nt * 8 + 2 * tg;
        float v0 = acc[nt][0] * scale, v1 = acc[nt][1] * scale;
        float v2 = acc[nt][2] * scale, v3 = acc[nt][3] * scale;
        if (BIAS) {
            float bA = __ldg(bias + c0), bB = __ldg(bias + c0 + 1);
            v0 += bA; v1 += bB; v2 += bA; v3 += bB;
        }
        if (ROUND) {
            v0 = __uint_as_float(f2tf(v0)); v1 = __uint_as_float(f2tf(v1));
            v2 = __uint_as_float(f2tf(v2)); v3 = __uint_as_float(f2tf(v3));
        }
        sDst[r0 * XP + c0]           = v0;
        sDst[r0 * XP + c0 + 1]       = v1;
        sDst[(r0 + 8) * XP + c0]     = v2;
        sDst[(r0 + 8) * XP + c0 + 1] = v3;
    }
}

__global__ void prep_kernel(const float* __restrict__ wqkv,
                            const float* __restrict__ wproj) {
    int i = blockIdx.x * blockDim.x + threadIdx.x;
    if (i < 128 * 384) g_wqkv[i] = __uint_as_float(f2tf(wqkv[i]));
    int j = i - 128 * 384;
    if (j >= 0 && j < 128 * 128) g_wproj[j] = __uint_as_float(f2tf(wproj[j]));
}

__global__ void __launch_bounds__(256, 1)
swin_attn_kernel(const float* __restrict__ x,
                 const float* __restrict__ bproj,
                 float* __restrict__ out) {
    extern __shared__ float smem[];
    float* sA  = smem + OFF_A;   // X -> V -> Y
    float* sC  = smem + OFF_C;   // Q -> O
    float* sE  = smem + OFF_E;   // K
    float* sW0 = smem + OFF_W0;  // Wq / Wv / P
    float* sW1 = smem + OFF_W1;  // Wk / Wproj

    const int tid  = threadIdx.x;
    const int wid  = tid >> 5;
    const int lane = tid & 31;

    const int win = blockIdx.x;
    const int b   = win >> 10;
    const int wh  = (win >> 5) & 31;
    const int ww  = win & 31;
    const int hs0 = wh * 8 + 4;   // +SS for the cyclic shift
    const int ws0 = ww * 8 + 4;

    const float* xb = x + b * (128 * 256 * 256);

    // -- prefetch Wq, gather shifted window X (tf32-rounded) ------------------
    stage_w(sW0, g_wqkv + 0, 384, tid);              // group: Wq

#pragma unroll
    for (int i = 0; i < 32; i++) {
        int idx = i * 256 + tid;
        int c = idx >> 6, l = idx & 63;
        int r = l >> 3, s = l & 7;
        int h = (hs0 + r) & 255;
        int w = (ws0 + s) & 255;
        float v = __ldg(xb + (c * 256 + h) * 256 + w);
        sA[l * XP + c] = __uint_as_float(f2tf(v));
    }
    wait_cp();
    __syncthreads();

    // -- QKV: three 64x128x128 GEMMs, double-buffered weight staging ----------
    stage_w(sW1, g_wqkv + 128, 384, tid);            // prefetch Wk
    gemm64<true, false, false>(sA, sW0, sC, wid, lane, SCALE_F, nullptr);  // Q (pre-scaled)
    wait_cp();
    __syncthreads();

    stage_w(sW0, g_wqkv + 256, 384, tid);            // prefetch Wv
    gemm64<true, false, false>(sA, sW1, sE, wid, lane, 1.f, nullptr);      // K
    wait_cp();
    __syncthreads();

    stage_w(sW1, g_wproj, 128, tid);                 // prefetch Wproj
    gemm64<true, false, true>(sA, sW0, sA, wid, lane, 1.f, nullptr);       // V (in place over X)
    __syncthreads();

    // -- attention: warp = (head, 32-row half) --------------------------------
    {
        const int hd = wid >> 1;
        const int rh = (wid & 1) * 32;
        const int g = lane >> 2, tg = lane & 3;

        float s[2][8][4];
#pragma unroll
        for (int mt = 0; mt < 2; mt++)
#pragma unroll
            for (int nt = 0; nt < 8; nt++) {
                s[mt][nt][0] = 0.f; s[mt][nt][1] = 0.f;
                s[mt][nt][2] = 0.f; s[mt][nt][3] = 0.f;
            }

        // S = Q Kh^T (Q already scaled)
#pragma unroll
        for (int k0 = 0; k0 < 32; k0 += 8) {
            unsigned a[2][4];
#pragma unroll
            for (int mt = 0; mt < 2; mt++) {
                const float* q0 = sC + (rh + mt * 16 + g) * XP + hd * 32 + k0 + tg;
                const float* q1 = q0 + 8 * XP;
                a[mt][0] = __float_as_uint(q0[0]);
                a[mt][1] = __float_as_uint(q1[0]);
                a[mt][2] = __float_as_uint(q0[4]);
                a[mt][3] = __float_as_uint(q1[4]);
            }
#pragma unroll
            for (int nt = 0; nt < 8; nt++) {
                const float* kr = sE + (nt * 8 + g) * XP + hd * 32 + k0 + tg;
                unsigned b0 = __float_as_uint(kr[0]);
                unsigned b1 = __float_as_uint(kr[4]);
                mma8(s[0][nt], a[0][0], a[0][1], a[0][2], a[0][3], b0, b1);
                mma8(s[1][nt], a[1][0], a[1][1], a[1][2], a[1][3], b0, b1);
            }
        }

        // softmax (rows spread over 4 lanes) -> normalized P into sW0 (swizzled)
        float* Ph = sW0 + hd * 4096;
#pragma unroll
        for (int mt = 0; mt < 2; mt++)
#pragma unroll
            for (int h2 = 0; h2 < 2; h2++) {
                float m = -3.0e38f;
#pragma unroll
                for (int nt = 0; nt < 8; nt++)
                    m = fmaxf(m, fmaxf(s[mt][nt][2 * h2], s[mt][nt][2 * h2 + 1]));
                m = fmaxf(m, __shfl_xor_sync(0xffffffffu, m, 1));
                m = fmaxf(m, __shfl_xor_sync(0xffffffffu, m, 2));
                float sum = 0.f;
                float e[16];
#pragma unroll
                for (int nt = 0; nt < 8; nt++) {
                    float e0 = __expf(s[mt][nt][2 * h2] - m);
                    float e1 = __expf(s[mt][nt][2 * h2 + 1] - m);
                    e[2 * nt] = e0; e[2 * nt + 1] = e1;
                    sum += e0 + e1;
                }
                sum += __shfl_xor_sync(0xffffffffu, sum, 1);
                sum += __shfl_xor_sync(0xffffffffu, sum, 2);
                float inv = 1.f / sum;
                int row = rh + mt * 16 + h2 * 8 + g;
                float* pr = Ph + row * 64;
                int sw = (g & 3) << 3;
#pragma unroll
                for (int nt = 0; nt < 8; nt++) {
                    int c = nt * 8 + 2 * tg;
                    pr[c ^ sw]       = __uint_as_float(f2tf(e[2 * nt] * inv));
                    pr[(c ^ sw) + 1] = __uint_as_float(f2tf(e[2 * nt + 1] * inv));
                }
            }
        __syncwarp();

        // O = P @ Vh -> written in place over this warp's own Q block
        float o[2][4][4];
#pragma unroll
        for (int mt = 0; mt < 2; mt++)
#pragma unroll
            for (int nt = 0; nt < 4; nt++) {
                o[mt][nt][0] = 0.f; o[mt][nt][1] = 0.f;
                o[mt][nt][2] = 0.f; o[mt][nt][3] = 0.f;
            }
        const int sw = (g & 3) << 3;
#pragma unroll
        for (int k0 = 0; k0 < 64; k0 += 8) {
            unsigned a[2][4];
#pragma unroll
            for (int mt = 0; mt < 2; mt++) {
                const float* p0 = Ph + (rh + mt * 16 + g) * 64;
                const float* p1 = p0 + 8 * 64;
                a[mt][0] = __float_as_uint(p0[(k0 + tg) ^ sw]);
                a[mt][1] = __float_as_uint(p1[(k0 + tg) ^ sw]);
                a[mt][2] = __float_as_uint(p0[(k0 + tg + 4) ^ sw]);
                a[mt][3] = __float_as_uint(p1[(k0 + tg + 4) ^ sw]);
            }
#pragma unroll
            for (int nt = 0; nt < 4; nt++) {
                const float* v0 = sA + (k0 + tg) * XP + hd * 32 + nt * 8 + g;
                const float* v1 = sA + (k0 + tg + 4) * XP + hd * 32 + nt * 8 + g;
                unsigned b0 = __float_as_uint(v0[0]);
                unsigned b1 = __float_as_uint(v1[0]);
                mma8(o[0][nt], a[0][0], a[0][1], a[0][2], a[0][3], b0, b1);
                mma8(o[1][nt], a[1][0], a[1][1], a[1][2], a[1][3], b0, b1);
            }
        }
#pragma unroll
        for (int mt = 0; mt < 2; mt++)
#pragma unroll
            for (int nt = 0; nt < 4; nt++) {
                int r0 = rh + mt * 16 + g;
                int c0 = hd * 32 + nt * 8 + 2 * tg;
                sC[r0 * XP + c0]           = __uint_as_float(f2tf(o[mt][nt][0]));
                sC[r0 * XP + c0 + 1]       = __uint_as_float(f2tf(o[mt][nt][1]));
                sC[(r0 + 8) * XP + c0]     = __uint_as_float(f2tf(o[mt][nt][2]));
                sC[(r0 + 8) * XP + c0 + 1] = __uint_as_float(f2tf(o[mt][nt][3]));
            }
    }

    wait_cp();          // Wproj staged long ago
    __syncthreads();    // all O visible

    // -- Y = O @ Wproj + bias -> sA ------------------------------------------
    gemm64<false, true, false>(sC, sW1, sA, wid, lane, 1.f, bproj);
    __syncthreads();

    // -- scatter with reverse cyclic shift, channels-first --------------------
#pragma unroll
    for (int i = 0; i < 32; i++) {
        int idx = i * 256 + tid;
        int c = idx >> 6, l = idx & 63;
        int r = l >> 3, s = l & 7;
        int h = (hs0 + r) & 255;
        int w = (ws0 + s) & 255;
        out[((b * 128 + c) * 256 + h) * 256 + w] = sA[l * XP + c];
    }
}

extern "C" void kernel_launch(void* const* d_in, const int* in_sizes, int n_in,
                              void* d_out, int out_size) {
    const float* x     = (const float*)d_in[0];
    const float* wqkv  = (const float*)d_in[1];
    const float* wproj = (const float*)d_in[2];
    const float* bproj = (const float*)d_in[3];
    float* out = (float*)d_out;

    prep_kernel<<<256, 256>>>(wqkv, wproj);

    cudaFuncSetAttribute(swin_attn_kernel,
                         cudaFuncAttributeMaxDynamicSharedMemorySize, SMEM_BYTES);
    swin_attn_kernel<<<8192, 256, SMEM_BYTES>>>(x, bproj, out);
}

// round 6
// speedup vs baseline: 1.9193x; 1.9193x over previous
#include <cuda_runtime.h>
#include <cuda_fp16.h>
#include <cstdint>

// ---------------------------------------------------------------------------
// SwinStyleAttention, fp16 mma.sync path (fp32 accumulate everywhere).
// B=8, C=128, H=W=256, WS=8, SS=4, HEADS=4, DH=32.
// One CTA = 2 horizontally adjacent windows = 128 tokens. 4096 CTAs, 256 thr.
// ---------------------------------------------------------------------------

#define SCALE_F 0.17677669529663687f

// smem byte offsets (fp16 tiles: 128 rows x 128 cols = 32 KB, 256 B/row)
#define X_OFF   0          // X -> P scratch (warps 0-3)
#define Q_OFF   32768      // Q
#define K_OFF   65536      // K -> O
#define V_OFF   98304      // V -> Y (fp32, stride 130, spills into W0/W1 tail)
#define W0_OFF  131072     // Wq -> Wv -> P scratch (warps 4-7)
#define W1_OFF  163840     // Wk -> Wproj
#define Y_OFF   V_OFF
#define SMEM_TOTAL 196608

__device__ __align__(16) __half g_wh[4][16384];   // WqT, WkT, WvT, WprojT

// ---------------------------------------------------------------------------
__device__ __forceinline__ uint32_t s2u(const void* p) {
    uint32_t a;
    asm("{ .reg .u64 t; cvta.to.shared.u64 t, %1; cvt.u32.u64 %0, t; }" : "=r"(a) : "l"(p));
    return a;
}
// byte offset of (row, 16B-chunk) in a 256B-row tile, XOR-swizzled
__device__ __forceinline__ uint32_t xoff(int row, int chunk) {
    return (uint32_t)(row * 256 + ((chunk ^ (row & 7)) << 4));
}
// same for the 128B-row P tile
__device__ __forceinline__ uint32_t poff(int row, int chunk) {
    return (uint32_t)(row * 128 + ((chunk ^ (row & 7)) << 4));
}

__device__ __forceinline__ void ldm4(uint32_t r[4], uint32_t addr) {
    asm volatile("ldmatrix.sync.aligned.m8n8.x4.shared.b16 {%0,%1,%2,%3}, [%4];"
                 : "=r"(r[0]), "=r"(r[1]), "=r"(r[2]), "=r"(r[3]) : "r"(addr));
}
__device__ __forceinline__ void ldm4t(uint32_t r[4], uint32_t addr) {
    asm volatile("ldmatrix.sync.aligned.m8n8.x4.trans.shared.b16 {%0,%1,%2,%3}, [%4];"
                 : "=r"(r[0]), "=r"(r[1]), "=r"(r[2]), "=r"(r[3]) : "r"(addr));
}
__device__ __forceinline__ void mmaf16(float c[4], const uint32_t a[4],
                                       uint32_t b0, uint32_t b1) {
    asm volatile(
        "mma.sync.aligned.m16n8k16.row.col.f32.f16.f16.f32 "
        "{%0,%1,%2,%3},{%4,%5,%6,%7},{%8,%9},{%0,%1,%2,%3};"
        : "+f"(c[0]), "+f"(c[1]), "+f"(c[2]), "+f"(c[3])
        : "r"(a[0]), "r"(a[1]), "r"(a[2]), "r"(a[3]), "r"(b0), "r"(b1));
}

__device__ __forceinline__ void cp16(uint32_t dst, const void* src) {
    asm volatile("cp.async.cg.shared.global [%0], [%1], 16;" :: "r"(dst), "l"(src));
}
#define CP_COMMIT() asm volatile("cp.async.commit_group;" ::: "memory")
#define CP_WAIT1()  asm volatile("cp.async.wait_group 1;" ::: "memory")
#define CP_WAIT0()  asm volatile("cp.async.wait_group 0;" ::: "memory")

// stage a [128 n][128 k] fp16 transposed weight into the swizzled tile
__device__ __forceinline__ void stageW(uint32_t dstBase, const __half* src, int tid) {
#pragma unroll
    for (int i = 0; i < 8; i++) {
        int id = i * 256 + tid;          // 0..2047
        int n = id >> 4, ch = id & 15;
        cp16(dstBase + xoff(n, ch), src + n * 128 + ch * 8);
    }
    CP_COMMIT();
}

// ---------------------------------------------------------------------------
__global__ void prep_kernel(const float* __restrict__ wqkv,
                            const float* __restrict__ wproj) {
    int i = blockIdx.x * blockDim.x + threadIdx.x;   // 0..65535
    int m = i >> 14, n = (i >> 7) & 127, k = i & 127;
    float v = (m < 3) ? wqkv[k * 384 + m * 128 + n] : wproj[k * 128 + n];
    g_wh[m][n * 128 + k] = __float2half_rn(v);
}

// ---------------------------------------------------------------------------
// D[128,128] = A[128,128] @ B[128,128]; 8 warps, warp tile 32(M) x 64(N).
// EPI: 0 = scale+fp16 (Q), 1 = fp16 (K), 2 = fp16 (V), 3 = fp32+bias -> Y.
template <int EPI>
__device__ __forceinline__ void gemm128(uint32_t sb, char* smem, int aOff, int bOff,
                                        int dOff, const float* __restrict__ bias) {
    const int lane = threadIdx.x & 31, wid = threadIdx.x >> 5;
    const int g = lane >> 2, tg = lane & 3;
    const int lg = lane >> 3, lr = lane & 7;
    const int m0 = (wid >> 1) * 32, n0 = (wid & 1) * 64;

    float acc[2][8][4];
#pragma unroll
    for (int mi = 0; mi < 2; mi++)
#pragma unroll
        for (int nb = 0; nb < 8; nb++)
#pragma unroll
            for (int j = 0; j < 4; j++) acc[mi][nb][j] = 0.f;

#pragma unroll
    for (int ks = 0; ks < 8; ks++) {
        uint32_t a[2][4];
#pragma unroll
        for (int mi = 0; mi < 2; mi++) {
            int row = m0 + mi * 16 + (lg & 1) * 8 + lr;
            ldm4(a[mi], sb + aOff + xoff(row, ks * 2 + (lg >> 1)));
        }
#pragma unroll
        for (int ni = 0; ni < 4; ni++) {
            uint32_t bf[4];
            int row = n0 + ni * 16 + (lg >> 1) * 8 + lr;
            ldm4(bf, sb + bOff + xoff(row, ks * 2 + (lg & 1)));
#pragma unroll
            for (int mi = 0; mi < 2; mi++) {
                mmaf16(acc[mi][2 * ni], a[mi], bf[0], bf[1]);
                mmaf16(acc[mi][2 * ni + 1], a[mi], bf[2], bf[3]);
            }
        }
    }

    if (EPI == 3) __syncthreads();   // protect Y overlay of V/W0/W1 + O reads

#pragma unroll
    for (int mi = 0; mi < 2; mi++)
#pragma unroll
        for (int nb = 0; nb < 8; nb++) {
            int r = m0 + mi * 16 + g;
            int c = n0 + nb * 8 + 2 * tg;
            float v0 = acc[mi][nb][0], v1 = acc[mi][nb][1];
            float v2 = acc[mi][nb][2], v3 = acc[mi][nb][3];
            if (EPI == 0) { v0 *= SCALE_F; v1 *= SCALE_F; v2 *= SCALE_F; v3 *= SCALE_F; }
            if (EPI < 3) {
                *(__half2*)(smem + dOff + xoff(r, c >> 3) + (c & 7) * 2) =
                    __floats2half2_rn(v0, v1);
                *(__half2*)(smem + dOff + xoff(r + 8, c >> 3) + (c & 7) * 2) =
                    __floats2half2_rn(v2, v3);
            } else {
                float b0 = __ldg(bias + c), b1 = __ldg(bias + c + 1);
                float* Y = (float*)(smem + dOff);
                Y[r * 130 + c] = v0 + b0;
                Y[r * 130 + c + 1] = v1 + b1;
                Y[(r + 8) * 130 + c] = v2 + b0;
                Y[(r + 8) * 130 + c + 1] = v3 + b1;
            }
        }
}

// ---------------------------------------------------------------------------
__global__ void __launch_bounds__(256, 1)
swin_kernel(const float* __restrict__ x,
            const float* __restrict__ bproj,
            float* __restrict__ out) {
    extern __shared__ char smem[];
    const uint32_t sb = s2u(smem);
    const int tid = threadIdx.x, wid = tid >> 5, lane = tid & 31;
    const int g = lane >> 2, tg = lane & 3;
    const int lg = lane >> 3, lr = lane & 7;

    const int p = blockIdx.x;
    const int b = p >> 9, rm = p & 511;
    const int hs0 = (rm >> 4) * 8 + 4;      // +SS cyclic shift
    const int ws0 = (rm & 15) * 16 + 4;
    const float* xb = x + (size_t)b * (128 * 256 * 256);

    // ---- stage Wq, Wk; gather shifted X (fp16) -----------------------------
    stageW(sb + W0_OFF, g_wh[0], tid);
    stageW(sb + W1_OFF, g_wh[1], tid);
#pragma unroll 4
    for (int i = 0; i < 32; i++) {
        int idx = i * 256 + tid;            // 8192 channel-pair x token
        int c2 = idx >> 7, t = idx & 127;
        int r = (t >> 3) & 7, s16 = ((t >> 6) << 3) | (t & 7);
        int h = (hs0 + r) & 255, wv = (ws0 + s16) & 255;
        const float* src = xb + (size_t)(2 * c2) * 65536 + h * 256 + wv;
        float v0 = __ldg(src), v1 = __ldg(src + 65536);
        *(__half2*)(smem + X_OFF + xoff(t, c2 >> 2) + (c2 & 3) * 4) =
            __floats2half2_rn(v0, v1);
    }
    CP_WAIT0();
    __syncthreads();

    // ---- QKV projections (weights double-buffered via cp.async) ------------
    gemm128<0>(sb, smem, X_OFF, W0_OFF, Q_OFF, nullptr);   // Q (scaled)
    __syncthreads();                                       // Wq reads done
    stageW(sb + W0_OFF, g_wh[2], tid);                     // Wv -> W0
    gemm128<1>(sb, smem, X_OFF, W1_OFF, K_OFF, nullptr);   // K
    __syncthreads();                                       // Wk reads done
    stageW(sb + W1_OFF, g_wh[3], tid);                     // Wproj -> W1
    CP_WAIT1();                                            // Wv arrived
    __syncthreads();
    gemm128<2>(sb, smem, X_OFF, W0_OFF, V_OFF, nullptr);   // V
    __syncthreads();                                       // V visible; X, W0 free

    // ---- attention: warp = (window, head); 64x64 S, softmax, PV ------------
    {
        const int w = wid >> 2, hd = wid & 3;
        const int tb0 = w * 64;
        const int pO = (wid < 4) ? (X_OFF + wid * 8192) : (W0_OFF + (wid - 4) * 8192);

#pragma unroll 1
        for (int mi = 0; mi < 4; mi++) {
            float s[8][4];
#pragma unroll
            for (int nb = 0; nb < 8; nb++)
#pragma unroll
                for (int j = 0; j < 4; j++) s[nb][j] = 0.f;
#pragma unroll
            for (int ks = 0; ks < 2; ks++) {
                uint32_t a[4];
                int arow = tb0 + mi * 16 + (lg & 1) * 8 + lr;
                ldm4(a, sb + Q_OFF + xoff(arow, hd * 4 + ks * 2 + (lg >> 1)));
#pragma unroll
                for (int ni = 0; ni < 4; ni++) {
                    uint32_t bf[4];
                    int brow = tb0 + ni * 16 + (lg >> 1) * 8 + lr;
                    ldm4(bf, sb + K_OFF + xoff(brow, hd * 4 + ks * 2 + (lg & 1)));
                    mmaf16(s[2 * ni], a, bf[0], bf[1]);
                    mmaf16(s[2 * ni + 1], a, bf[2], bf[3]);
                }
            }
            // softmax on the two 8-row halves this thread touches
#pragma unroll
            for (int hf = 0; hf < 2; hf++) {
                float m = -3.0e38f;
#pragma unroll
                for (int nb = 0; nb < 8; nb++)
                    m = fmaxf(m, fmaxf(s[nb][2 * hf], s[nb][2 * hf + 1]));
                m = fmaxf(m, __shfl_xor_sync(0xffffffffu, m, 1));
                m = fmaxf(m, __shfl_xor_sync(0xffffffffu, m, 2));
                float e[16], sum = 0.f;
#pragma unroll
                for (int nb = 0; nb < 8; nb++) {
                    float e0 = __expf(s[nb][2 * hf] - m);
                    float e1 = __expf(s[nb][2 * hf + 1] - m);
                    e[2 * nb] = e0; e[2 * nb + 1] = e1; sum += e0 + e1;
                }
                sum += __shfl_xor_sync(0xffffffffu, sum, 1);
                sum += __shfl_xor_sync(0xffffffffu, sum, 2);
                float inv = 1.f / sum;
                int r = mi * 16 + hf * 8 + g;
#pragma unroll
                for (int nb = 0; nb < 8; nb++) {
                    int c = nb * 8 + 2 * tg;
                    *(__half2*)(smem + pO + poff(r, c >> 3) + (c & 7) * 2) =
                        __floats2half2_rn(e[2 * nb] * inv, e[2 * nb + 1] * inv);
                }
            }
        }
        __syncwarp();

        // O = P @ V_head -> overwrite own K slot
#pragma unroll 1
        for (int mi = 0; mi < 4; mi++) {
            float o[4][4];
#pragma unroll
            for (int nb = 0; nb < 4; nb++)
#pragma unroll
                for (int j = 0; j < 4; j++) o[nb][j] = 0.f;
#pragma unroll
            for (int tk = 0; tk < 4; tk++) {
                uint32_t a[4];
                int arow = mi * 16 + (lg & 1) * 8 + lr;
                ldm4(a, sb + pO + poff(arow, tk * 2 + (lg >> 1)));
#pragma unroll
                for (int dp = 0; dp < 2; dp++) {
                    uint32_t bf[4];
                    int brow = tb0 + tk * 16 + (lg & 1) * 8 + lr;
                    ldm4t(bf, sb + V_OFF + xoff(brow, hd * 4 + dp * 2 + (lg >> 1)));
                    mmaf16(o[2 * dp], a, bf[0], bf[1]);
                    mmaf16(o[2 * dp + 1], a, bf[2], bf[3]);
                }
            }
#pragma unroll
            for (int nb = 0; nb < 4; nb++) {
                int r = tb0 + mi * 16 + g;
                int c = hd * 32 + nb * 8 + 2 * tg;
                *(__half2*)(smem + K_OFF + xoff(r, c >> 3) + (c & 7) * 2) =
                    __floats2half2_rn(o[nb][0], o[nb][1]);
                *(__half2*)(smem + K_OFF + xoff(r + 8, c >> 3) + (c & 7) * 2) =
                    __floats2half2_rn(o[nb][2], o[nb][3]);
            }
        }
    }
    __syncthreads();       // all O visible
    CP_WAIT0();            // Wproj arrived

    // ---- Y = O @ WprojT + bias (fp32, into V/W0 region, stride 130) --------
    gemm128<3>(sb, smem, K_OFF, W1_OFF, Y_OFF, bproj);
    __syncthreads();

    // ---- reverse-shift scatter, channels-first -----------------------------
    const float* Y = (const float*)(smem + Y_OFF);
#pragma unroll 4
    for (int i = 0; i < 64; i++) {
        int idx = i * 256 + tid;            // 16384 (c, t)
        int c = idx >> 7, t = idx & 127;
        int r = (t >> 3) & 7, s16 = ((t >> 6) << 3) | (t & 7);
        int h = (hs0 + r) & 255, wv = (ws0 + s16) & 255;
        out[(((size_t)b * 128 + c) * 256 + h) * 256 + wv] = Y[t * 130 + c];
    }
}

extern "C" void kernel_launch(void* const* d_in, const int* in_sizes, int n_in,
                              void* d_out, int out_size) {
    const float* x     = (const float*)d_in[0];
    const float* wqkv  = (const float*)d_in[1];
    const float* wproj = (const float*)d_in[2];
    const float* bproj = (const float*)d_in[3];
    float* out = (float*)d_out;

    prep_kernel<<<256, 256>>>(wqkv, wproj);

    cudaFuncSetAttribute(swin_kernel,
                         cudaFuncAttributeMaxDynamicSharedMemorySize, SMEM_TOTAL);
    swin_kernel<<<4096, 256, SMEM_TOTAL>>>(x, bproj, out);
}